// round 6
// baseline (speedup 1.0000x reference)
#include <cuda_runtime.h>
#include <cuda_bf16.h>

// DiagPooling: x [B=8, C=128, H=512, W=512] fp32 -> out [B, 1, 513] fp32
// out[b, 0, o] = (1 / (128 * (512 - |o-256|))) * sum_{c,i} x[b, c, i, i + o - 256]
//
// Flat uniform float4 decomposition (correctness proven in R4):
//   Pair row p (p<256, cols [0, p+256], aligned start at 0) with row p+256
//   (cols [p, 511], start aligned DOWN to p&~3). Slot counts
//   nvec1 = (p>>2)+65 and 128-(p>>2) sum to EXACTLY 193 for every p.
// Channel split x2 (64 channels per thread-item):
//   items = 8 * 256 * 2 * 193 = 790,528 = 3088 blocks x 256 threads.
//   Every lane active, every block identical. 64x LDG.128 per thread
//   (50M loads chip-wide, 4x fewer than the scalar R1 kernel).
// NO __launch_bounds__ occupancy forcing -> registers float (~40), no
// local-memory spills (the R5 failure). Pre-scaled atomicAdd direct to
// d_out; zero-init kernel first (d_out is poisoned by the harness).

#define B_DIM 8
#define C_DIM 128
#define H_DIM 512
#define W_DIM 512
#define N_OFF 513
#define OUT_ELEMS (B_DIM * N_OFF)       // 4104

#define C_SLICES 2
#define C_PER_SLICE (C_DIM / C_SLICES)  // 64
#define SLOTS_PER_PAIR 193
#define TOTAL_ITEMS (B_DIM * 256 * C_SLICES * SLOTS_PER_PAIR)  // 790528
#define NBLOCKS (TOTAL_ITEMS / 256)                            // 3088

__global__ void zero_out_kernel(float* __restrict__ out, int n) {
    int idx = blockIdx.x * blockDim.x + threadIdx.x;
    if (idx < n) out[idx] = 0.0f;
}

__global__ __launch_bounds__(256) void diag_pool_kernel(
    const float* __restrict__ x, float* __restrict__ out)
{
    const int g = blockIdx.x * 256 + threadIdx.x;   // global item id

    // decode: g = (((b*256 + p)*2 + cs)*193 + s)
    const int s  = g % SLOTS_PER_PAIR;
    const int q1 = g / SLOTS_PER_PAIR;
    const int cs = q1 & 1;
    const int q2 = q1 >> 1;
    const int p  = q2 & 255;
    const int b  = q2 >> 8;

    const int nvec1 = (p >> 2) + 65;

    int i, jbase;
    if (s < nvec1) {                      // row p, cols [0, p+256]
        i = p;
        jbase = 4 * s;
    } else {                              // row p+256, cols [p, 511]
        i = p + 256;
        jbase = (p & ~3) + 4 * (s - nvec1);
    }

    const size_t S = (size_t)H_DIM * W_DIM;     // channel stride (elements)
    const float* ptr = x + ((size_t)b * C_DIM + (size_t)cs * C_PER_SLICE) * S
                         + (size_t)i * W_DIM + jbase;

    // Two independent accumulator sets (8 regs) + 2 float4 loads in flight
    // per unrolled step; unroll 4 -> 8 independent LDG.128 outstanding.
    float ax0 = 0.f, ay0 = 0.f, az0 = 0.f, aw0 = 0.f;
    float ax1 = 0.f, ay1 = 0.f, az1 = 0.f, aw1 = 0.f;

    #pragma unroll 4
    for (int c = 0; c < C_PER_SLICE; c += 2) {
        const float4 v0 = __ldg((const float4*)(ptr + (size_t)(c + 0) * S));
        const float4 v1 = __ldg((const float4*)(ptr + (size_t)(c + 1) * S));
        ax0 += v0.x; ay0 += v0.y; az0 += v0.z; aw0 += v0.w;
        ax1 += v1.x; ay1 += v1.y; az1 += v1.z; aw1 += v1.w;
    }

    float sum[4];
    sum[0] = ax0 + ax1;
    sum[1] = ay0 + ay1;
    sum[2] = az0 + az1;
    sum[3] = aw0 + aw1;

    // valid column window for this row
    const int jlo = (i >= 256) ? (i - 256) : 0;
    const int jhi = (i <= 255) ? (i + 256) : (H_DIM - 1);

    float* dst = out + b * N_OFF;

    #pragma unroll
    for (int k = 0; k < 4; k++) {
        const int j = jbase + k;
        if (j >= jlo && j <= jhi) {
            const int o = j - i + 256;    // diagonal id 0..512
            const int off = o - 256;
            const int dlen = H_DIM - (off < 0 ? -off : off);
            atomicAdd(dst + o, sum[k] / ((float)C_DIM * (float)dlen));
        }
    }
}

extern "C" void kernel_launch(void* const* d_in, const int* in_sizes, int n_in,
                              void* d_out, int out_size) {
    const float* x = (const float*)d_in[0];
    float* out = (float*)d_out;

    zero_out_kernel<<<(OUT_ELEMS + 255) / 256, 256>>>(out, OUT_ELEMS);

    diag_pool_kernel<<<NBLOCKS, 256>>>(x, out);
}

// round 7
// speedup vs baseline: 1.2501x; 1.2501x over previous
#include <cuda_runtime.h>
#include <cuda_bf16.h>

// DiagPooling: x [B=8, C=128, H=512, W=512] fp32 -> out [B, 1, 513] fp32
// out[b, 0, o] = (1 / (128 * (512 - |o-256|))) * sum_{c,i} x[b, c, i, i + o - 256]
//
// Diagonal-register formulation: thread owns a FIXED diagonal o (off = o-256)
// and walks rows i, so its element address advances by 513 floats (2052 B)
// per step -> sequential, DRAM-row-friendly stream (vs the 1 MiB channel
// stride of earlier rounds). Accumulation stays in a register; one
// pre-scaled atomicAdd per thread at the end.
//
// Block = (c, b, half) where half selects i in [0,256) or [256,512).
//   half 0: valid offsets o in [1, 512]  (off=-256 has no i<256)
//           per-lane i0 = max(0, -off), i1 = 256 (uniform)
//   half 1: valid offsets o in [0, 511]  (off=+256 has no i>=256)
//           per-lane i0 = 256 (uniform), i1 = 512 - max(0, off)
// Exactly 512 offsets per half -> 512 threads, every lane mapped.
// Within a warp (32 consecutive offsets) only one bound varies, spread <=31:
// loop warp-uniformly over [min i0, max i1) with a per-lane predicate.
// Per row i the block's active lanes read a CONTIGUOUS span of the plane
// (coalesced ~2KB bursts). Same bytes and same 201M scalar loads as R1.

#define B_DIM 8
#define C_DIM 128
#define H_DIM 512
#define W_DIM 512
#define N_OFF 513
#define OUT_ELEMS (B_DIM * N_OFF)

__global__ void zero_out_kernel(float* __restrict__ out, int n) {
    int idx = blockIdx.x * blockDim.x + threadIdx.x;
    if (idx < n) out[idx] = 0.0f;
}

__global__ __launch_bounds__(512) void diag_pool_kernel(
    const float* __restrict__ x, float* __restrict__ out)
{
    const int c    = blockIdx.x;     // channel 0..127
    const int b    = blockIdx.y;     // batch 0..7
    const int half = blockIdx.z;     // 0: i in [0,256), 1: i in [256,512)
    const int lane = threadIdx.x;    // 0..511

    // offset for this thread
    const int o   = lane + (half == 0 ? 1 : 0);   // half0: 1..512, half1: 0..511
    const int off = o - 256;

    // per-lane valid i range within this half
    int i0, i1;
    if (half == 0) {
        i0 = (off < 0) ? -off : 0;   // i >= -off
        i1 = 256;
    } else {
        i0 = 256;
        i1 = (off > 0) ? (512 - off) : 512;   // i < 512 - off
    }

    // warp-uniform loop bounds (offsets consecutive within a warp -> spread <= 31)
    const unsigned i0w = __reduce_min_sync(0xffffffffu, (unsigned)i0);
    const unsigned i1w = __reduce_max_sync(0xffffffffu, (unsigned)i1);

    // element at row i: plane[i*512 + i + off] = (plane + off)[i*513]
    const float* p = x + ((size_t)(b * C_DIM + c)) * ((size_t)H_DIM * W_DIM) + off;

    float a0 = 0.f, a1 = 0.f, a2 = 0.f, a3 = 0.f;

    int i = (int)i0w;
    const int iend = (int)i1w;

    // main loop: 8 independent predicated loads in flight per thread
    for (; i + 8 <= iend; i += 8) {
        #pragma unroll
        for (int m = 0; m < 8; m++) {
            const int ii = i + m;
            if (ii >= i0 && ii < i1) {
                const float v = __ldg(p + (size_t)ii * (W_DIM + 1));
                if (m & 1) { if (m & 2) a3 += v; else a1 += v; }
                else       { if (m & 2) a2 += v; else a0 += v; }
            }
        }
    }
    for (; i < iend; i++) {
        if (i >= i0 && i < i1) a0 += __ldg(p + (size_t)i * (W_DIM + 1));
    }

    const float s = (a0 + a1) + (a2 + a3);

    const int dlen = H_DIM - (off < 0 ? -off : off);
    atomicAdd(&out[b * N_OFF + o], s / ((float)C_DIM * (float)dlen));
}

extern "C" void kernel_launch(void* const* d_in, const int* in_sizes, int n_in,
                              void* d_out, int out_size) {
    const float* x = (const float*)d_in[0];
    float* out = (float*)d_out;

    zero_out_kernel<<<(OUT_ELEMS + 255) / 256, 256>>>(out, OUT_ELEMS);

    dim3 grid(C_DIM, B_DIM, 2);   // 128 x 8 x 2 = 2048 blocks
    diag_pool_kernel<<<grid, 512>>>(x, out);
}

// round 8
// speedup vs baseline: 1.5711x; 1.2568x over previous
#include <cuda_runtime.h>
#include <cuda_bf16.h>
#include <string.h>

// DiagPooling: x [B=8, C=128, H=512, W=512] fp32 -> out [B, 1, 513] fp32
// out[b, 0, o] = (1 / (128 * (512 - |o-256|))) * sum_{c,i} x[b, c, i, i + o - 256]
//
// R1 structure (best: 128.4us, DRAM 83.6%), plus two scheduling fixes:
//  1. LPT block order: block x maps to row i sorted by DESCENDING width
//     (widest/middle rows first), so the drain tail consists of the
//     shortest blocks. d = 255 - (x>>1); i = (x&1) ? 511-d : d.
//  2. d_out zero-init via cudaMemsetAsync (graph memset node) instead of
//     a kernel launch.
// Mapping (unchanged from R1): block = (x, b), 512 threads; thread t owns
// column j = j0 + t of row i (coalesced), sums all 128 channels in
// registers (4 accumulators, unroll 8 -> 32 independent LDGs in flight),
// then one pre-scaled atomicAdd into out[b*513 + (j-i+256)].

#define B_DIM 8
#define C_DIM 128
#define H_DIM 512
#define W_DIM 512
#define N_OFF 513
#define OUT_ELEMS (B_DIM * N_OFF)

__global__ __launch_bounds__(512) void diag_pool_kernel(
    const float* __restrict__ x, float* __restrict__ out)
{
    // LPT row permutation: widest rows (middle) first, narrowest (edges) last
    const int xblk = blockIdx.x;                 // 0..511
    const int d = 255 - (xblk >> 1);             // 255..0
    const int i = (xblk & 1) ? (511 - d) : d;    // row, width-descending order

    const int b = blockIdx.y;                    // batch 0..7
    const int t = threadIdx.x;                   // 0..511

    // Valid column range for this row: |j - i| <= 256
    const int j0 = (i - 256 > 0) ? (i - 256) : 0;
    const int j1 = (i + 256 < H_DIM - 1) ? (i + 256) : (H_DIM - 1);
    const int j = j0 + t;
    if (j > j1) return;

    // Base pointer: x[b, 0, i, j]; channel stride = H*W elements
    const size_t ch_stride = (size_t)H_DIM * W_DIM;
    const float* p = x + ((size_t)b * C_DIM * H_DIM + (size_t)i) * W_DIM + j;

    // Sum over all 128 channels with 4 independent accumulators
    float s0 = 0.f, s1 = 0.f, s2 = 0.f, s3 = 0.f;
    #pragma unroll 8
    for (int c = 0; c < C_DIM; c += 4) {
        s0 += __ldg(p + (size_t)(c + 0) * ch_stride);
        s1 += __ldg(p + (size_t)(c + 1) * ch_stride);
        s2 += __ldg(p + (size_t)(c + 2) * ch_stride);
        s3 += __ldg(p + (size_t)(c + 3) * ch_stride);
    }
    const float s = (s0 + s1) + (s2 + s3);

    // Diagonal/output index and normalization
    const int o = j - i + 256;                   // 0..512, unique within block
    const int off = o - 256;
    const int diag_len = H_DIM - (off < 0 ? -off : off);
    const float denom = (float)C_DIM * (float)diag_len;

    atomicAdd(&out[b * N_OFF + o], s / denom);
}

extern "C" void kernel_launch(void* const* d_in, const int* in_sizes, int n_in,
                              void* d_out, int out_size) {
    const float* x = (const float*)d_in[0];
    float* out = (float*)d_out;

    // zero d_out (poisoned by harness) via a graph-capturable memset node
    cudaMemsetAsync(out, 0, OUT_ELEMS * sizeof(float));

    dim3 grid(H_DIM, B_DIM);
    diag_pool_kernel<<<grid, 512>>>(x, out);
}